// round 1
// baseline (speedup 1.0000x reference)
#include <cuda_runtime.h>
#include <cstdint>

// Problem constants
#define NI   1024      // rows (n_i)
#define NC   201       // classes incl. background
#define TT   100       // temporal snippets
#define NPAIR (NI*NC)  // 205824

// -------- scratch (no allocations allowed) --------
__device__ int            g_lab[NI * TT];   // argmax label per (n,t)
__device__ unsigned char  g_flags[NI];      // bit0=bg, bit1=sel_rare, bit2=sel_common
__device__ double         g_acc;            // global accumulator

// ======================= threefry2x32 (JAX-exact) =======================
__host__ __device__ constexpr uint32_t rotl32(uint32_t x, int r) {
    return (x << r) | (x >> (32 - r));
}
struct TF2 { uint32_t a, b; };

__host__ __device__ constexpr TF2 tf2x32(uint32_t k0, uint32_t k1,
                                         uint32_t x0, uint32_t x1) {
    uint32_t ks0 = k0, ks1 = k1, ks2 = k0 ^ k1 ^ 0x1BD11BDAu;
    uint32_t kk[3] = {ks0, ks1, ks2};
    const int R0[4] = {13, 15, 26, 6};
    const int R1[4] = {17, 29, 16, 24};
    uint32_t v0 = x0 + ks0, v1 = x1 + ks1;
    for (int i = 0; i < 5; i++) {
        for (int j = 0; j < 4; j++) {
            int r = (i % 2 == 0) ? R0[j] : R1[j];
            v0 += v1; v1 = rotl32(v1, r); v1 ^= v0;
        }
        v0 += kk[(i + 1) % 3];
        v1 += kk[(i + 2) % 3] + (uint32_t)(i + 1);
    }
    return TF2{v0, v1};
}

// jax.random.key(42) -> key data (0, 42)
// keys = split(key, 100): counts = iota(200), halves x0=[0..99], x1=[100..199]
// keys[99] = (out[198], out[199]) = (second_out(lane 98), second_out(lane 99))
constexpr TF2      S98  = tf2x32(0u, 42u, 98u, 198u);
constexpr TF2      S99  = tf2x32(0u, 42u, 99u, 199u);
constexpr uint32_t KLA  = S98.b, KLB = S99.b;           // keys[99]
// k1, k2 = split(keys[99]): counts = iota(4), lanes (0,2) and (1,3)
constexpr TF2      SP0  = tf2x32(KLA, KLB, 0u, 2u);
constexpr TF2      SP1  = tf2x32(KLA, KLB, 1u, 3u);
constexpr uint32_t K1A = SP0.a, K1B = SP1.a;            // k1 = (y0_l0, y0_l1)
constexpr uint32_t K2A = SP0.b, K2B = SP1.b;            // k2 = (y1_l0, y1_l1)

// uniform(key, (1024,)): bits = threefry(key, iota(1024)); halves [0..511],[512..1023]
__device__ __forceinline__ float tf_uniform(uint32_t ka, uint32_t kb, int n) {
    TF2 r = (n < 512) ? tf2x32(ka, kb, (uint32_t)n,          (uint32_t)(n + 512))
                      : tf2x32(ka, kb, (uint32_t)(n - 512),  (uint32_t)n);
    uint32_t bits = (n < 512) ? r.a : r.b;
    return __uint_as_float((bits >> 9) | 0x3f800000u) - 1.0f;
}

// ======================= K1: per-(n,t) argmax over c =======================
// labels_[n, c, t] at n*NC*TT + c*TT + t; warp reads 32 consecutive t -> coalesced.
__global__ void k_argmax(const float* __restrict__ labels) {
    if (blockIdx.x == 0 && threadIdx.x == 0) g_acc = 0.0;   // reset accumulator
    int n = blockIdx.x;
    int t = threadIdx.x;
    if (t >= TT) return;
    const float* p = labels + (size_t)n * (NC * TT) + t;
    float best = p[0];
    int   bi   = 0;
    #pragma unroll 4
    for (int c = 1; c < NC; c++) {
        float v = p[(size_t)c * TT];
        if (v > best) { best = v; bi = c; }   // strict > : first-max (argmax semantics)
    }
    g_lab[n * TT + t] = bi;
}

// ======================= K2: bg flags + rank-based subsample ===============
__global__ void k_flags() {
    __shared__ int   bgIdx[NI];
    __shared__ float bgU1[NI];
    __shared__ float bgU2[NI];
    __shared__ int   cnt;
    int n = threadIdx.x;
    if (n == 0) cnt = 0;
    __syncthreads();

    int  lab99 = g_lab[n * TT + (TT - 1)];
    bool bg    = (lab99 == NC - 1);       // label == 200
    float u1 = 0.f, u2 = 0.f;
    if (bg) {
        u1 = tf_uniform(K1A, K1B, n);
        u2 = tf_uniform(K2A, K2B, n);
        int pos = atomicAdd(&cnt, 1);
        bgIdx[pos] = n; bgU1[pos] = u1; bgU2[pos] = u2;
    }
    __syncthreads();

    int nbg = cnt;
    int kr  = nbg / 100;   // int(len(bg)*0.01)
    int kc  = nbg / 10;    // int(len(bg)*0.10)
    unsigned f = 0;
    if (bg) {
        f = 1u;
        // stable-argsort rank among bg rows (non-bg rows are +inf, always after)
        int r1 = 0, r2 = 0;
        for (int i = 0; i < nbg; i++) {
            float a = bgU1[i], b = bgU2[i];
            int   m = bgIdx[i];
            r1 += (a < u1) || (a == u1 && m < n);
            r2 += (b < u2) || (b == u2 && m < n);
        }
        if (r1 < kr) f |= 2u;
        if (r2 < kc) f |= 4u;
    }
    g_flags[n] = (unsigned char)f;
}

// ======================= K3: main fused reduction ==========================
// One warp per (n,c). 32 warps/block, grid = NPAIR/32 = 6432 exactly.
__global__ __launch_bounds__(1024) void k_main(const float* __restrict__ cls) {
    __shared__ double wsum[32];
    int warp = threadIdx.x >> 5;
    int lane = threadIdx.x & 31;
    int p = blockIdx.x * 32 + warp;           // 0 .. NPAIR-1
    int n = p / NC;
    int c = p - n * NC;

    const float* base = cls + (size_t)n * (NC * TT) + (size_t)c * TT;
    const int*   labn = g_lab + n * TT;

    float ssp = 0.f, ssel = 0.f;
    float x99v = 0.f;
    int   lab99v = -1;
    #pragma unroll
    for (int j = 0; j < 4; j++) {
        int t = lane + 32 * j;
        if (t < TT) {
            float x  = __ldg(base + t);
            int   lb = __ldg(labn + t);
            // softplus(x) = max(x,0) + log1p(exp(-|x|))
            float sp = fmaxf(x, 0.f) + __logf(1.f + __expf(-fabsf(x)));
            ssp += sp;
            if (lb == c) ssel += x;           // target * x subtraction
            if (j == 3) { x99v = x; lab99v = lb; }   // lane 3 holds t=99
        }
    }
    float v = ssp - ssel;
    #pragma unroll
    for (int o = 16; o; o >>= 1) v += __shfl_xor_sync(0xffffffffu, v, o);
    float x99   = __shfl_sync(0xffffffffu, x99v,   3);
    int   lab99 = __shfl_sync(0xffffffffu, lab99v, 3);

    if (lane == 0) {
        unsigned f = g_flags[n];
        bool wm;
        if (f & 1u) {
            // bg row: FREQ(150..199) + BG(200) always; rare(0..49)/common(50..149) if selected
            wm = (c >= 150) || ((f & 2u) && c < 50) || ((f & 4u) && c >= 50 && c < 150);
        } else {
            // non-bg row: target one-hot OR sigmoid(x99) >= 0.3
            float s = 1.f / (1.f + __expf(-x99));
            wm = (c == lab99) || (s >= 0.3f);
        }
        wsum[warp] = wm ? (double)v : 0.0;
    }
    __syncthreads();
    if (warp == 0) {
        double s = wsum[lane];
        #pragma unroll
        for (int o = 16; o; o >>= 1) s += __shfl_xor_sync(0xffffffffu, s, o);
        if (lane == 0) atomicAdd(&g_acc, s);
    }
}

// ======================= K4: finalize ======================================
__global__ void k_final(float* __restrict__ out) {
    out[0] = (float)(g_acc * (1.0 / ((double)NI * (double)TT)));
}

// ======================= launcher ==========================================
extern "C" void kernel_launch(void* const* d_in, const int* in_sizes, int n_in,
                              void* d_out, int out_size) {
    const float* cls    = (const float*)d_in[0];   // cls_logits_ [1024,201,100]
    const float* labels = (const float*)d_in[1];   // labels_     [1024,201,100]
    float* out = (float*)d_out;

    k_argmax<<<NI, 128>>>(labels);
    k_flags <<<1, NI>>>();
    k_main  <<<NPAIR / 32, 1024>>>(cls);
    k_final <<<1, 1>>>(out);
}

// round 2
// speedup vs baseline: 1.4565x; 1.4565x over previous
#include <cuda_runtime.h>
#include <cstdint>
#include <math_constants.h>

#define NI   1024
#define NC   201
#define TT   100
#define ROW  (NC * TT)          // 20100

// -------- scratch (no allocations allowed; zero-init at module load) --------
__device__ float          g_v[NI * NC];     // deferred v for bg rows only
__device__ unsigned char  g_isbg[NI];       // per-row bg flag (rewritten every run)
__device__ double         g_acc;            // zero at load; K2 resets after use

// ======================= threefry2x32 (JAX-exact) =======================
__host__ __device__ constexpr uint32_t rotl32(uint32_t x, int r) {
    return (x << r) | (x >> (32 - r));
}
struct TF2 { uint32_t a, b; };

__host__ __device__ constexpr TF2 tf2x32(uint32_t k0, uint32_t k1,
                                         uint32_t x0, uint32_t x1) {
    uint32_t ks2 = k0 ^ k1 ^ 0x1BD11BDAu;
    uint32_t kk[3] = {k0, k1, ks2};
    const int R0[4] = {13, 15, 26, 6};
    const int R1[4] = {17, 29, 16, 24};
    uint32_t v0 = x0 + k0, v1 = x1 + k1;
    for (int i = 0; i < 5; i++) {
        for (int j = 0; j < 4; j++) {
            int r = (i % 2 == 0) ? R0[j] : R1[j];
            v0 += v1; v1 = rotl32(v1, r); v1 ^= v0;
        }
        v0 += kk[(i + 1) % 3];
        v1 += kk[(i + 2) % 3] + (uint32_t)(i + 1);
    }
    return TF2{v0, v1};
}

// key(42) -> (0,42); keys = split(key,100); keys[99] from counts (98,198),(99,199)
constexpr TF2      S98 = tf2x32(0u, 42u, 98u, 198u);
constexpr TF2      S99 = tf2x32(0u, 42u, 99u, 199u);
constexpr uint32_t KLA = S98.b, KLB = S99.b;
// k1,k2 = split(keys[99]): counts (0,2) and (1,3)
constexpr TF2      SP0 = tf2x32(KLA, KLB, 0u, 2u);
constexpr TF2      SP1 = tf2x32(KLA, KLB, 1u, 3u);
constexpr uint32_t K1A = SP0.a, K1B = SP1.a;
constexpr uint32_t K2A = SP0.b, K2B = SP1.b;

__device__ __forceinline__ float tf_uniform(uint32_t ka, uint32_t kb, int n) {
    TF2 r = (n < 512) ? tf2x32(ka, kb, (uint32_t)n,         (uint32_t)(n + 512))
                      : tf2x32(ka, kb, (uint32_t)(n - 512), (uint32_t)n);
    uint32_t bits = (n < 512) ? r.a : r.b;
    return __uint_as_float((bits >> 9) | 0x3f800000u) - 1.0f;
}

// softplus(x) = max(x,0) + log1p(exp(-|x|))
__device__ __forceinline__ float sp(float x) {
    return fmaxf(x, 0.f) + __logf(1.f + __expf(-fabsf(x)));
}

// ======================= K1: fused per-row kernel ==========================
// One block per row n. Phase A: cooperative argmax over c (8 warps split the
// class range; each lane holds 4 consecutive t's via float4 -> 400B warp txn).
// Phase B: stream cls row, per-class BCE sums; non-bg rows accumulate wm*v
// immediately (1 double atomic per block); bg rows defer v to g_v.
__global__ __launch_bounds__(256) void k_fused(const float* __restrict__ cls,
                                               const float* __restrict__ labels) {
    __shared__ float  sBest[8][100];
    __shared__ int    sBi[8][100];
    __shared__ int    sLab[100];
    __shared__ double sSum[8];
    __shared__ int    sBg;

    int n    = blockIdx.x;
    int tid  = threadIdx.x;
    int w    = tid >> 5;
    int lane = tid & 31;

    const float* lrow = labels + (size_t)n * ROW;

    // ---- phase A: per-warp partial argmax over strided class subset ----
    if (lane < 25) {
        float b0 = -CUDART_INF_F, b1 = -CUDART_INF_F,
              b2 = -CUDART_INF_F, b3 = -CUDART_INF_F;
        int i0 = 0, i1 = 0, i2 = 0, i3 = 0;
        #pragma unroll 4
        for (int c = w; c < NC; c += 8) {
            float4 v = __ldg((const float4*)(lrow + c * TT) + lane);
            if (v.x > b0) { b0 = v.x; i0 = c; }
            if (v.y > b1) { b1 = v.y; i1 = c; }
            if (v.z > b2) { b2 = v.z; i2 = c; }
            if (v.w > b3) { b3 = v.w; i3 = c; }
        }
        int t = lane * 4;
        sBest[w][t + 0] = b0; sBi[w][t + 0] = i0;
        sBest[w][t + 1] = b1; sBi[w][t + 1] = i1;
        sBest[w][t + 2] = b2; sBi[w][t + 2] = i2;
        sBest[w][t + 3] = b3; sBi[w][t + 3] = i3;
    }
    __syncthreads();

    // ---- combine 8 warp-partials; first-max tie-break (lower c wins) ----
    if (tid < TT) {
        float b = sBest[0][tid]; int bi = sBi[0][tid];
        #pragma unroll
        for (int ww = 1; ww < 8; ww++) {
            float v = sBest[ww][tid]; int c = sBi[ww][tid];
            if (v > b || (v == b && c < bi)) { b = v; bi = c; }
        }
        sLab[tid] = bi;
        if (tid == TT - 1) {
            int ib = (bi == NC - 1);
            sBg = ib;
            g_isbg[n] = (unsigned char)ib;
        }
    }
    __syncthreads();

    bool isbg  = (sBg != 0);
    int  lab99 = sLab[TT - 1];
    const float* crow = cls + (size_t)n * ROW;

    // ---- phase B: per-class BCE reduction ----
    double wacc = 0.0;
    for (int c = w; c < NC; c += 8) {
        float ssp = 0.f, ssel = 0.f, xw = 0.f;
        if (lane < 25) {
            float4 x = __ldg((const float4*)(crow + c * TT) + lane);
            int t = lane * 4;
            ssp = sp(x.x) + sp(x.y) + sp(x.z) + sp(x.w);
            if (sLab[t + 0] == c) ssel += x.x;
            if (sLab[t + 1] == c) ssel += x.y;
            if (sLab[t + 2] == c) ssel += x.z;
            if (sLab[t + 3] == c) ssel += x.w;
            xw = x.w;                       // lane 24 holds t=99
        }
        float v = ssp - ssel;
        #pragma unroll
        for (int o = 16; o; o >>= 1) v += __shfl_xor_sync(0xffffffffu, v, o);
        float x99 = __shfl_sync(0xffffffffu, xw, 24);

        if (lane == 0) {
            if (isbg) {
                g_v[n * NC + c] = v;        // defer: wm needs cross-row ranks
            } else {
                float s = 1.f / (1.f + __expf(-x99));
                if (c == lab99 || s >= 0.3f) wacc += (double)v;
            }
        }
    }
    if (lane == 0) sSum[w] = wacc;
    __syncthreads();
    if (tid == 0 && !isbg) {
        double s = 0.0;
        #pragma unroll
        for (int i = 0; i < 8; i++) s += sSum[i];
        atomicAdd(&g_acc, s);
    }
}

// ======================= K2: bg tail + finalize ============================
__global__ __launch_bounds__(256) void k_tail(float* __restrict__ out) {
    __shared__ int           bgIdx[NI];
    __shared__ float         bgU1[NI];
    __shared__ float         bgU2[NI];
    __shared__ unsigned char bgSel[NI];
    __shared__ int           cnt;
    __shared__ double        wsum[8];

    int tid = threadIdx.x;
    if (tid == 0) cnt = 0;
    __syncthreads();

    // compact bg rows (order irrelevant; ranks tie-break on original index)
    for (int n = tid; n < NI; n += 256) {
        if (g_isbg[n]) {
            int p = atomicAdd(&cnt, 1);
            bgIdx[p] = n;
            bgU1[p]  = tf_uniform(K1A, K1B, n);
            bgU2[p]  = tf_uniform(K2A, K2B, n);
        }
    }
    __syncthreads();

    int nbg = cnt;
    int kr  = nbg / 100;    // int(n_bg * 0.01)
    int kc  = nbg / 10;     // int(n_bg * 0.10)

    // stable-argsort ranks among bg rows (non-bg rows are +inf, always after)
    for (int i = tid; i < nbg; i += 256) {
        float u1 = bgU1[i], u2 = bgU2[i];
        int   m  = bgIdx[i];
        int r1 = 0, r2 = 0;
        for (int j = 0; j < nbg; j++) {
            float a = bgU1[j], b = bgU2[j];
            int   mj = bgIdx[j];
            r1 += (a < u1) || (a == u1 && mj < m);
            r2 += (b < u2) || (b == u2 && mj < m);
        }
        bgSel[i] = (unsigned char)((r1 < kr ? 2u : 0u) | (r2 < kc ? 4u : 0u));
    }
    __syncthreads();

    // sum deferred bg contributions
    double acc = 0.0;
    int total = nbg * NC;
    for (int q = tid; q < total; q += 256) {
        int i = q / NC;
        int c = q - i * NC;
        unsigned f = bgSel[i];
        // bg wm: FREQ(150..199)+BG(200) always; rare(0..49)/common(50..149) if selected
        bool wm = (c >= 150) || ((f & 2u) && c < 50) ||
                  ((f & 4u) && c >= 50 && c < 150);
        if (wm) acc += (double)g_v[bgIdx[i] * NC + c];
    }
    // block reduce
    #pragma unroll
    for (int o = 16; o; o >>= 1) acc += __shfl_xor_sync(0xffffffffu, acc, o);
    int w = tid >> 5, lane = tid & 31;
    if (lane == 0) wsum[w] = acc;
    __syncthreads();
    if (tid == 0) {
        double s = 0.0;
        #pragma unroll
        for (int i = 0; i < 8; i++) s += wsum[i];
        double tot = g_acc + s;
        out[0] = (float)(tot * (1.0 / ((double)NI * (double)TT)));
        g_acc = 0.0;     // reset for next graph replay (determinism)
    }
}

// ======================= launcher ==========================================
extern "C" void kernel_launch(void* const* d_in, const int* in_sizes, int n_in,
                              void* d_out, int out_size) {
    const float* cls    = (const float*)d_in[0];   // [1024,201,100]
    const float* labels = (const float*)d_in[1];   // [1024,201,100]
    float* out = (float*)d_out;

    k_fused<<<NI, 256>>>(cls, labels);
    k_tail <<<1, 256>>>(out);
}